// round 2
// baseline (speedup 1.0000x reference)
#include <cuda_runtime.h>
#include <cstdint>
#include <cstdio>

#define IN_DIM  2048
#define OUT_DIM 5632
#define M_TOT   8192
#define GROUP   128

// Scratch (static __device__ arrays -- allowed; no runtime allocation)
__device__ float g_Weff[(size_t)OUT_DIM * IN_DIM];   // dequantized W + folded LoRA, tf32-rounded
__device__ float g_At[16 * IN_DIM];                  // At[r][i] = 2.0 * lora_A[i][r]

__device__ __forceinline__ float tf32_rna(float x) {
    uint32_t u;
    asm("cvt.rna.tf32.f32 %0, %1;" : "=r"(u) : "f"(x));
    return __uint_as_float(u);
}

// ---------------------------------------------------------------------------
// Kernel 1: transpose lora_A and fold in LORA_SCALE (=2.0)
// ---------------------------------------------------------------------------
__global__ void prep_At_kernel(const float* __restrict__ lora_A) {
    int idx = blockIdx.x * blockDim.x + threadIdx.x;   // over IN_DIM*16
    if (idx >= IN_DIM * 16) return;
    int i = idx >> 4;
    int r = idx & 15;
    g_At[r * IN_DIM + i] = 2.0f * lora_A[idx];
}

// ---------------------------------------------------------------------------
// Kernel 2: dequant int4 + fold LoRA:  Weff[o][i] = (q-z)*s + sum_r At[r][i]*B[r][o]
// Each thread: 4 output rows (o), 8 consecutive i.  Warp-uniform o => B loads broadcast.
// ---------------------------------------------------------------------------
__global__ void dequant_fold_kernel(const int*   __restrict__ packed,
                                    const float* __restrict__ scales,
                                    const float* __restrict__ zeros,
                                    const float* __restrict__ lora_B) {
    const int ib = threadIdx.x;          // 0..255 -> i0 = 8*ib
    const int oq = blockIdx.x;           // 0..1407
    const int i0 = ib * 8;

    float acc[4][8];
#pragma unroll
    for (int j = 0; j < 4; j++)
#pragma unroll
        for (int k = 0; k < 8; k++) acc[j][k] = 0.0f;

    // LoRA contribution
#pragma unroll
    for (int r = 0; r < 16; r++) {
        const float4 a0 = *reinterpret_cast<const float4*>(&g_At[r * IN_DIM + i0]);
        const float4 a1 = *reinterpret_cast<const float4*>(&g_At[r * IN_DIM + i0 + 4]);
#pragma unroll
        for (int j = 0; j < 4; j++) {
            const int o = oq + j * (OUT_DIM / 4);
            const float bv = lora_B[r * OUT_DIM + o];
            acc[j][0] += a0.x * bv;  acc[j][1] += a0.y * bv;
            acc[j][2] += a0.z * bv;  acc[j][3] += a0.w * bv;
            acc[j][4] += a1.x * bv;  acc[j][5] += a1.y * bv;
            acc[j][6] += a1.z * bv;  acc[j][7] += a1.w * bv;
        }
    }

    // Dequant + store (tf32-rounded so the GEMM's B operand is exactly tf32)
#pragma unroll
    for (int j = 0; j < 4; j++) {
        const int o = oq + j * (OUT_DIM / 4);
        const int4 pk = *reinterpret_cast<const int4*>(&packed[(size_t)o * (IN_DIM / 2) + ib * 4]);
        const int g = o * (IN_DIM / GROUP) + (ib >> 4);
        const float s = scales[g];
        const float z = zeros[g];

        int v;
        v = pk.x; acc[j][0] += ((v & 15) - z) * s;  acc[j][1] += (((v >> 4) & 15) - z) * s;
        v = pk.y; acc[j][2] += ((v & 15) - z) * s;  acc[j][3] += (((v >> 4) & 15) - z) * s;
        v = pk.z; acc[j][4] += ((v & 15) - z) * s;  acc[j][5] += (((v >> 4) & 15) - z) * s;
        v = pk.w; acc[j][6] += ((v & 15) - z) * s;  acc[j][7] += (((v >> 4) & 15) - z) * s;

        float4 r0 = make_float4(tf32_rna(acc[j][0]), tf32_rna(acc[j][1]),
                                tf32_rna(acc[j][2]), tf32_rna(acc[j][3]));
        float4 r1 = make_float4(tf32_rna(acc[j][4]), tf32_rna(acc[j][5]),
                                tf32_rna(acc[j][6]), tf32_rna(acc[j][7]));
        *reinterpret_cast<float4*>(&g_Weff[(size_t)o * IN_DIM + i0])     = r0;
        *reinterpret_cast<float4*>(&g_Weff[(size_t)o * IN_DIM + i0 + 4]) = r1;
    }
}

// ---------------------------------------------------------------------------
// Kernel 3: GEMM  C[8192][5632] = X[8192][2048] * Weff^T   (tf32 mma.sync)
// Block tile 128x128x32, 256 threads (8 warps, 2x4), warp tile 64x32.
// cp.async double-buffered, XOR-swizzled smem, ldmatrix.x4 b16 trick for tf32.
// ---------------------------------------------------------------------------
#define BM 128
#define BN 128
#define BK 32
#define STAGE_BYTES (2 * BM * BK * 4)   /* A tile + B tile per stage = 32768 */

__device__ __forceinline__ void ldsm4(uint32_t& r0, uint32_t& r1, uint32_t& r2, uint32_t& r3,
                                      uint32_t addr) {
    asm volatile("ldmatrix.sync.aligned.m8n8.x4.shared.b16 {%0,%1,%2,%3}, [%4];"
                 : "=r"(r0), "=r"(r1), "=r"(r2), "=r"(r3) : "r"(addr));
}

__device__ __forceinline__ void mma_tf32(float* d, const uint32_t* a, const uint32_t* b) {
    asm volatile(
        "mma.sync.aligned.m16n8k8.row.col.f32.tf32.tf32.f32 "
        "{%0,%1,%2,%3}, {%4,%5,%6,%7}, {%8,%9}, {%0,%1,%2,%3};"
        : "+f"(d[0]), "+f"(d[1]), "+f"(d[2]), "+f"(d[3])
        : "r"(a[0]), "r"(a[1]), "r"(a[2]), "r"(a[3]), "r"(b[0]), "r"(b[1]));
}

extern __shared__ float smem_gemm[];

__global__ __launch_bounds__(256, 2) void gemm_kernel(const float* __restrict__ X,
                                                      float* __restrict__ C) {
    const int tid   = threadIdx.x;
    const int lane  = tid & 31;
    const int warp  = tid >> 5;
    const int warpM = warp >> 2;   // 0..1 (64-row slabs)
    const int warpN = warp & 3;    // 0..3 (32-col slabs)
    const int m0 = blockIdx.y * BM;
    const int n0 = blockIdx.x * BN;

    const uint32_t sbase = (uint32_t)__cvta_generic_to_shared(smem_gemm);

    // --- cp.async source/dest mapping: thread covers 4 consecutive 16B chunks of one row
    const int ldrow = tid >> 1;          // 0..127
    const int ldcb  = (tid & 1) * 4;     // first chunk (of 8) in the row
    const float* gA = X      + (size_t)(m0 + ldrow) * IN_DIM + ldcb * 4;
    const float* gB = g_Weff + (size_t)(n0 + ldrow) * IN_DIM + ldcb * 4;
    uint32_t sAoff[4], sBoff[4];
#pragma unroll
    for (int i = 0; i < 4; i++) {
        const int cb = ldcb + i;
        const int sw = cb ^ (ldrow & 7);
        sAoff[i] = ldrow * 128 + sw * 16;
        sBoff[i] = (uint32_t)(BM * BK * 4) + ldrow * 128 + sw * 16;
    }

    // --- ldmatrix per-lane addressing constants
    const int mtx   = lane >> 3;                                // which 8x8 matrix
    const int x7    = lane & 7;
    const int aRowB = warpM * 64 + ((mtx & 1) << 3) + x7;       // A: rows, matrices {0,1}->m, {2,3}->k+4
    const int kcA   = mtx >> 1;
    const int bRowB = warpN * 32 + ((mtx >> 1) << 3) + x7;      // B: matrices {0,1}->k halves, {2,3}->n+8
    const int kcB   = mtx & 1;

    float acc[4][4][4];
#pragma unroll
    for (int mi = 0; mi < 4; mi++)
#pragma unroll
        for (int ni = 0; ni < 4; ni++)
#pragma unroll
            for (int e = 0; e < 4; e++) acc[mi][ni][e] = 0.0f;

    const int nk = IN_DIM / BK;   // 64

    // prologue: stage 0
    {
        const uint32_t st = sbase;
#pragma unroll
        for (int i = 0; i < 4; i++) {
            asm volatile("cp.async.cg.shared.global [%0], [%1], 16;" :: "r"(st + sAoff[i]), "l"(gA + i * 4));
            asm volatile("cp.async.cg.shared.global [%0], [%1], 16;" :: "r"(st + sBoff[i]), "l"(gB + i * 4));
        }
        asm volatile("cp.async.commit_group;");
    }

    for (int kt = 0; kt < nk; kt++) {
        if (kt + 1 < nk) {
            const uint32_t st = sbase + ((kt + 1) & 1) * STAGE_BYTES;
            const float* a = gA + (size_t)(kt + 1) * BK;
            const float* b = gB + (size_t)(kt + 1) * BK;
#pragma unroll
            for (int i = 0; i < 4; i++) {
                asm volatile("cp.async.cg.shared.global [%0], [%1], 16;" :: "r"(st + sAoff[i]), "l"(a + i * 4));
                asm volatile("cp.async.cg.shared.global [%0], [%1], 16;" :: "r"(st + sBoff[i]), "l"(b + i * 4));
            }
            asm volatile("cp.async.commit_group;");
            asm volatile("cp.async.wait_group 1;");
        } else {
            asm volatile("cp.async.wait_group 0;");
        }
        __syncthreads();

        const uint32_t stA = sbase + (kt & 1) * STAGE_BYTES;
        const uint32_t stB = stA + (uint32_t)(BM * BK * 4);

#pragma unroll
        for (int ks = 0; ks < 4; ks++) {
            uint32_t a[4][4];
#pragma unroll
            for (int mi = 0; mi < 4; mi++) {
                const uint32_t addr = stA + (uint32_t)(aRowB + mi * 16) * 128
                                          + ((uint32_t)((ks * 2 + kcA) ^ x7) << 4);
                ldsm4(a[mi][0], a[mi][1], a[mi][2], a[mi][3], addr);
            }
            uint32_t b[4][2];
#pragma unroll
            for (int ni2 = 0; ni2 < 2; ni2++) {
                uint32_t r0, r1, r2, r3;
                const uint32_t addr = stB + (uint32_t)(bRowB + ni2 * 16) * 128
                                          + ((uint32_t)((ks * 2 + kcB) ^ x7) << 4);
                ldsm4(r0, r1, r2, r3, addr);
                b[ni2 * 2][0] = r0;  b[ni2 * 2][1] = r1;
                b[ni2 * 2 + 1][0] = r2;  b[ni2 * 2 + 1][1] = r3;
            }
            // round X fragments to tf32 (rna) to kill truncation bias
#pragma unroll
            for (int mi = 0; mi < 4; mi++)
#pragma unroll
                for (int e = 0; e < 4; e++)
                    asm("cvt.rna.tf32.f32 %0, %1;" : "=r"(a[mi][e]) : "f"(__uint_as_float(a[mi][e])));
#pragma unroll
            for (int mi = 0; mi < 4; mi++)
#pragma unroll
                for (int ni = 0; ni < 4; ni++)
                    mma_tf32(acc[mi][ni], a[mi], b[ni]);
        }
        __syncthreads();
    }

    // epilogue: direct stores (float2 per c-pair, sector-aligned)
    const int g  = lane >> 2;
    const int t4 = lane & 3;
#pragma unroll
    for (int mi = 0; mi < 4; mi++) {
        const int row = m0 + warpM * 64 + mi * 16 + g;
#pragma unroll
        for (int ni = 0; ni < 4; ni++) {
            const int col = n0 + warpN * 32 + ni * 8 + t4 * 2;
            *reinterpret_cast<float2*>(&C[(size_t)row * OUT_DIM + col]) =
                make_float2(acc[mi][ni][0], acc[mi][ni][1]);
            *reinterpret_cast<float2*>(&C[(size_t)(row + 8) * OUT_DIM + col]) =
                make_float2(acc[mi][ni][2], acc[mi][ni][3]);
        }
    }
}

// ---------------------------------------------------------------------------
extern "C" void kernel_launch(void* const* d_in, const int* in_sizes, int n_in,
                              void* d_out, int out_size) {
    const float* x      = (const float*)d_in[0];
    const int*   packed = (const int*)  d_in[1];
    const float* scales = (const float*)d_in[2];
    const float* zeros  = (const float*)d_in[3];
    const float* lora_A = (const float*)d_in[4];
    const float* lora_B = (const float*)d_in[5];
    float* out = (float*)d_out;

    prep_At_kernel<<<(IN_DIM * 16 + 255) / 256, 256>>>(lora_A);
    dequant_fold_kernel<<<OUT_DIM / 4, 256>>>(packed, scales, zeros, lora_B);

    cudaFuncSetAttribute(gemm_kernel, cudaFuncAttributeMaxDynamicSharedMemorySize, 2 * STAGE_BYTES);
    dim3 grid(OUT_DIM / BN, M_TOT / BM);
    gemm_kernel<<<grid, 256, 2 * STAGE_BYTES>>>(x, out);
}

// round 9
// speedup vs baseline: 2.4088x; 2.4088x over previous
#include <cuda_runtime.h>
#include <cuda_fp16.h>
#include <cstdint>
#include <cstdio>

#define IN_DIM  2048
#define OUT_DIM 5632
#define M_TOT   8192
#define GROUP   128

// GEMM tiling (fp16 operands, fp32 accumulate)
#define BM 256
#define BN 128
#define BKH 64                       /* k-halves per tile = 128 B/row */
#define NKT (IN_DIM / BKH)           /* 32 */
#define A_ST (BM * 128)              /* 32768 */
#define B_ST (BN * 128)              /* 16384 */
#define ST_BYTES (A_ST + B_ST)       /* 49152 */
#define STAGES 4
#define SMEM_TOTAL (STAGES * ST_BYTES)  /* 196608 */

// Static device scratch (no runtime allocation)
__device__ __align__(16) __half g_Xh[(size_t)M_TOT * IN_DIM];    // X in fp16
__device__ __align__(16) __half g_Wh[(size_t)OUT_DIM * IN_DIM];  // dequant W + LoRA, fp16
__device__ __align__(16) float  g_At[16 * IN_DIM];               // 2.0 * lora_A^T

// ---------------------------------------------------------------------------
// prep: At[r][i] = 2 * lora_A[i][r]
// ---------------------------------------------------------------------------
__global__ void prep_At_kernel(const float* __restrict__ lora_A) {
    int idx = blockIdx.x * blockDim.x + threadIdx.x;
    if (idx >= IN_DIM * 16) return;
    int i = idx >> 4;
    int r = idx & 15;
    g_At[r * IN_DIM + i] = 2.0f * lora_A[idx];
}

// ---------------------------------------------------------------------------
// convert X -> fp16 (one pass; mainloop does zero converts)
// ---------------------------------------------------------------------------
__global__ void conv_x_kernel(const float* __restrict__ X) {
    size_t i = ((size_t)blockIdx.x * blockDim.x + threadIdx.x) * 8;
    if (i >= (size_t)M_TOT * IN_DIM) return;
    float4 v0 = *reinterpret_cast<const float4*>(X + i);
    float4 v1 = *reinterpret_cast<const float4*>(X + i + 4);
    __half2 h0 = __floats2half2_rn(v0.x, v0.y);
    __half2 h1 = __floats2half2_rn(v0.z, v0.w);
    __half2 h2 = __floats2half2_rn(v1.x, v1.y);
    __half2 h3 = __floats2half2_rn(v1.z, v1.w);
    uint4 u;
    u.x = *reinterpret_cast<uint32_t*>(&h0);
    u.y = *reinterpret_cast<uint32_t*>(&h1);
    u.z = *reinterpret_cast<uint32_t*>(&h2);
    u.w = *reinterpret_cast<uint32_t*>(&h3);
    *reinterpret_cast<uint4*>(g_Xh + i) = u;
}

// ---------------------------------------------------------------------------
// dequant int4 + fold LoRA into Wh (fp16):
//   Wh[o][i] = fp16( (q-z)*s + sum_r At[r][i]*B[r][o] )
// ---------------------------------------------------------------------------
__global__ void dequant_fold_kernel(const int*   __restrict__ packed,
                                    const float* __restrict__ scales,
                                    const float* __restrict__ zeros,
                                    const float* __restrict__ lora_B) {
    const int ib = threadIdx.x;          // 0..255 -> i0 = 8*ib
    const int oq = blockIdx.x;           // 0..1407
    const int i0 = ib * 8;

    float acc[4][8];
#pragma unroll
    for (int j = 0; j < 4; j++)
#pragma unroll
        for (int k = 0; k < 8; k++) acc[j][k] = 0.0f;

#pragma unroll
    for (int r = 0; r < 16; r++) {
        const float4 a0 = *reinterpret_cast<const float4*>(&g_At[r * IN_DIM + i0]);
        const float4 a1 = *reinterpret_cast<const float4*>(&g_At[r * IN_DIM + i0 + 4]);
#pragma unroll
        for (int j = 0; j < 4; j++) {
            const int o = oq + j * (OUT_DIM / 4);
            const float bv = lora_B[r * OUT_DIM + o];
            acc[j][0] += a0.x * bv;  acc[j][1] += a0.y * bv;
            acc[j][2] += a0.z * bv;  acc[j][3] += a0.w * bv;
            acc[j][4] += a1.x * bv;  acc[j][5] += a1.y * bv;
            acc[j][6] += a1.z * bv;  acc[j][7] += a1.w * bv;
        }
    }

#pragma unroll
    for (int j = 0; j < 4; j++) {
        const int o = oq + j * (OUT_DIM / 4);
        const int4 pk = *reinterpret_cast<const int4*>(&packed[(size_t)o * (IN_DIM / 2) + ib * 4]);
        const int g = o * (IN_DIM / GROUP) + (ib >> 4);
        const float s = scales[g];
        const float z = zeros[g];

        int v;
        v = pk.x; acc[j][0] += ((v & 15) - z) * s;  acc[j][1] += (((v >> 4) & 15) - z) * s;
        v = pk.y; acc[j][2] += ((v & 15) - z) * s;  acc[j][3] += (((v >> 4) & 15) - z) * s;
        v = pk.z; acc[j][4] += ((v & 15) - z) * s;  acc[j][5] += (((v >> 4) & 15) - z) * s;
        v = pk.w; acc[j][6] += ((v & 15) - z) * s;  acc[j][7] += (((v >> 4) & 15) - z) * s;

        __half2 h0 = __floats2half2_rn(acc[j][0], acc[j][1]);
        __half2 h1 = __floats2half2_rn(acc[j][2], acc[j][3]);
        __half2 h2 = __floats2half2_rn(acc[j][4], acc[j][5]);
        __half2 h3 = __floats2half2_rn(acc[j][6], acc[j][7]);
        uint4 u;
        u.x = *reinterpret_cast<uint32_t*>(&h0);
        u.y = *reinterpret_cast<uint32_t*>(&h1);
        u.z = *reinterpret_cast<uint32_t*>(&h2);
        u.w = *reinterpret_cast<uint32_t*>(&h3);
        *reinterpret_cast<uint4*>(&g_Wh[(size_t)o * IN_DIM + i0]) = u;
    }
}

// ---------------------------------------------------------------------------
// GEMM: C[8192][5632] = Xh * Wh^T  (fp16 mma.sync m16n8k16, fp32 accum)
// CTA tile 256x128xBK64, 256 threads (8 warps = 4x2), warp tile 64x64.
// 4-stage cp.async ring, SW128 xor swizzle, one __syncthreads per k-tile.
// ---------------------------------------------------------------------------
__device__ __forceinline__ void ldsm4(uint32_t& r0, uint32_t& r1, uint32_t& r2, uint32_t& r3,
                                      uint32_t addr) {
    asm volatile("ldmatrix.sync.aligned.m8n8.x4.shared.b16 {%0,%1,%2,%3}, [%4];"
                 : "=r"(r0), "=r"(r1), "=r"(r2), "=r"(r3) : "r"(addr));
}

__device__ __forceinline__ void mma_f16(float* d, const uint32_t* a, const uint32_t* b) {
    asm volatile(
        "mma.sync.aligned.m16n8k16.row.col.f32.f16.f16.f32 "
        "{%0,%1,%2,%3}, {%4,%5,%6,%7}, {%8,%9}, {%0,%1,%2,%3};"
        : "+f"(d[0]), "+f"(d[1]), "+f"(d[2]), "+f"(d[3])
        : "r"(a[0]), "r"(a[1]), "r"(a[2]), "r"(a[3]), "r"(b[0]), "r"(b[1]));
}

extern __shared__ char smem_g[];

__global__ __launch_bounds__(256, 1) void gemm_kernel(float* __restrict__ C) {
    const int tid   = threadIdx.x;
    const int lane  = tid & 31;
    const int warp  = tid >> 5;
    const int warpM = warp >> 1;     // 0..3  (64-row slabs)
    const int warpN = warp & 1;      // 0..1  (64-col slabs)
    const int n0 = blockIdx.x * BN;
    const int m0 = blockIdx.y * BM;

    const uint32_t sb = (uint32_t)__cvta_generic_to_shared(smem_g);

    // ---- per-thread load plan: 12 x 16B chunks per stage (3072 total)
    const __half* srcp[12];
    uint32_t      dsto[12];
#pragma unroll
    for (int i = 0; i < 12; i++) {
        const int c = tid + i * 256;          // 0..3071
        if (c < 2048) {                       // A chunk: 256 rows x 8 chunks
            const int row = c >> 3, col = c & 7;
            srcp[i] = g_Xh + (size_t)(m0 + row) * IN_DIM + col * 8;
            dsto[i] = (uint32_t)(row * 128 + ((col ^ (row & 7)) << 4));
        } else {                              // B chunk: 128 rows x 8 chunks
            const int cc = c - 2048;
            const int row = cc >> 3, col = cc & 7;
            srcp[i] = g_Wh + (size_t)(n0 + row) * IN_DIM + col * 8;
            dsto[i] = (uint32_t)(A_ST + row * 128 + ((col ^ (row & 7)) << 4));
        }
    }

    // ---- ldmatrix per-lane constants
    const int mtx = lane >> 3;       // 8x8 matrix id
    const int x7  = lane & 7;
    // A: mats {0,1} = m rows 0-7/8-15 (khalf 0), {2,3} = same rows khalf 1
    const int aRow = warpM * 64 + ((mtx & 1) << 3) + x7;
    const int kcA  = mtx >> 1;       // k-half (16B chunk within k16 step)
    // B: mats {0,1} = n rows 0-7 khalf 0/1, {2,3} = n rows 8-15 khalf 0/1
    const int bRow = warpN * 64 + ((mtx >> 1) << 3) + x7;
    const int kcB  = mtx & 1;

    float acc[4][8][4];
#pragma unroll
    for (int mi = 0; mi < 4; mi++)
#pragma unroll
        for (int ni = 0; ni < 8; ni++)
#pragma unroll
            for (int e = 0; e < 4; e++) acc[mi][ni][e] = 0.0f;

    // prologue: fill stages 0..2
#pragma unroll
    for (int j = 0; j < STAGES - 1; j++) {
        const uint32_t st = sb + j * ST_BYTES;
#pragma unroll
        for (int i = 0; i < 12; i++)
            asm volatile("cp.async.cg.shared.global [%0], [%1], 16;"
                         :: "r"(st + dsto[i]), "l"(srcp[i] + j * BKH));
        asm volatile("cp.async.commit_group;");
    }

    for (int kt = 0; kt < NKT; kt++) {
        asm volatile("cp.async.wait_group 2;");
        __syncthreads();   // stage kt visible to all; slot (kt+3)&3 free (kt-1 compute done)

        // prefetch stage kt+3 into slot (kt+3)&3
        {
            const int j = kt + STAGES - 1;
            if (j < NKT) {
                const uint32_t st = sb + (j & (STAGES - 1)) * ST_BYTES;
#pragma unroll
                for (int i = 0; i < 12; i++)
                    asm volatile("cp.async.cg.shared.global [%0], [%1], 16;"
                                 :: "r"(st + dsto[i]), "l"(srcp[i] + j * BKH));
            }
            asm volatile("cp.async.commit_group;");   // empty at tail keeps counts uniform
        }

        const uint32_t stA = sb + (kt & (STAGES - 1)) * ST_BYTES;
        const uint32_t stB = stA + (uint32_t)A_ST;

#pragma unroll
        for (int ks = 0; ks < 4; ks++) {   // 4 x k16 covers BKH=64
            uint32_t a[4][4];
#pragma unroll
            for (int mi = 0; mi < 4; mi++) {
                const uint32_t addr = stA + (uint32_t)(aRow + mi * 16) * 128
                                          + ((uint32_t)((ks * 2 + kcA) ^ x7) << 4);
                ldsm4(a[mi][0], a[mi][1], a[mi][2], a[mi][3], addr);
            }
            uint32_t b[8][2];
#pragma unroll
            for (int nb = 0; nb < 4; nb++) {
                uint32_t r0, r1, r2, r3;
                const uint32_t addr = stB + (uint32_t)(bRow + nb * 16) * 128
                                          + ((uint32_t)((ks * 2 + kcB) ^ x7) << 4);
                ldsm4(r0, r1, r2, r3, addr);
                b[nb * 2][0] = r0;      b[nb * 2][1] = r1;
                b[nb * 2 + 1][0] = r2;  b[nb * 2 + 1][1] = r3;
            }
#pragma unroll
            for (int mi = 0; mi < 4; mi++)
#pragma unroll
                for (int ni = 0; ni < 8; ni++)
                    mma_f16(acc[mi][ni], a[mi], b[ni]);
        }
    }

    // epilogue: direct float2 stores
    const int g  = lane >> 2;
    const int t4 = lane & 3;
#pragma unroll
    for (int mi = 0; mi < 4; mi++) {
        const int row = m0 + warpM * 64 + mi * 16 + g;
#pragma unroll
        for (int ni = 0; ni < 8; ni++) {
            const int col = n0 + warpN * 64 + ni * 8 + t4 * 2;
            *reinterpret_cast<float2*>(&C[(size_t)row * OUT_DIM + col]) =
                make_float2(acc[mi][ni][0], acc[mi][ni][1]);
            *reinterpret_cast<float2*>(&C[(size_t)(row + 8) * OUT_DIM + col]) =
                make_float2(acc[mi][ni][2], acc[mi][ni][3]);
        }
    }
}

// ---------------------------------------------------------------------------
extern "C" void kernel_launch(void* const* d_in, const int* in_sizes, int n_in,
                              void* d_out, int out_size) {
    const float* x      = (const float*)d_in[0];
    const int*   packed = (const int*)  d_in[1];
    const float* scales = (const float*)d_in[2];
    const float* zeros  = (const float*)d_in[3];
    const float* lora_A = (const float*)d_in[4];
    const float* lora_B = (const float*)d_in[5];
    float* out = (float*)d_out;

    prep_At_kernel<<<(IN_DIM * 16 + 255) / 256, 256>>>(lora_A);
    conv_x_kernel<<<(int)(((size_t)M_TOT * IN_DIM / 8 + 255) / 256), 256>>>(x);
    dequant_fold_kernel<<<OUT_DIM / 4, 256>>>(packed, scales, zeros, lora_B);

    cudaFuncSetAttribute(gemm_kernel, cudaFuncAttributeMaxDynamicSharedMemorySize,
                         SMEM_TOTAL);
    dim3 grid(OUT_DIM / BN, M_TOT / BM);
    gemm_kernel<<<grid, 256, SMEM_TOTAL>>>(out);
}

// round 11
// speedup vs baseline: 2.6888x; 1.1163x over previous
#include <cuda_runtime.h>
#include <cuda_fp16.h>
#include <cstdint>
#include <cstdio>

#define IN_DIM  2048
#define OUT_DIM 5632
#define M_TOT   8192
#define GROUP   128

// GEMM tiling (fp16 operands, fp32 accumulate)
#define BM 128
#define BN 128
#define BKH 64                       /* k-halves per tile = 128 B/row */
#define NKT (IN_DIM / BKH)           /* 32 */
#define A_ST (BM * 128)              /* 16384 */
#define B_ST (BN * 128)              /* 16384 */
#define ST_BYTES (A_ST + B_ST)       /* 32768 */
#define STAGES 3
#define SMEM_TOTAL (STAGES * ST_BYTES)  /* 98304 -> 2 CTAs/SM */

// Static device scratch (no runtime allocation)
__device__ __align__(16) __half g_Xh[(size_t)M_TOT * IN_DIM];    // X in fp16
__device__ __align__(16) __half g_Wh[(size_t)OUT_DIM * IN_DIM];  // dequant W + LoRA, fp16
__device__ __align__(16) float  g_At[16 * IN_DIM];               // 2.0 * lora_A^T

// ---------------------------------------------------------------------------
// prep: At[r][i] = 2 * lora_A[i][r]
// ---------------------------------------------------------------------------
__global__ void prep_At_kernel(const float* __restrict__ lora_A) {
    int idx = blockIdx.x * blockDim.x + threadIdx.x;
    if (idx >= IN_DIM * 16) return;
    int i = idx >> 4;
    int r = idx & 15;
    g_At[r * IN_DIM + i] = 2.0f * lora_A[idx];
}

// ---------------------------------------------------------------------------
// convert X -> fp16 (one pass; mainloop does zero converts)
// ---------------------------------------------------------------------------
__global__ void conv_x_kernel(const float* __restrict__ X) {
    size_t i = ((size_t)blockIdx.x * blockDim.x + threadIdx.x) * 8;
    if (i >= (size_t)M_TOT * IN_DIM) return;
    float4 v0 = *reinterpret_cast<const float4*>(X + i);
    float4 v1 = *reinterpret_cast<const float4*>(X + i + 4);
    __half2 h0 = __floats2half2_rn(v0.x, v0.y);
    __half2 h1 = __floats2half2_rn(v0.z, v0.w);
    __half2 h2 = __floats2half2_rn(v1.x, v1.y);
    __half2 h3 = __floats2half2_rn(v1.z, v1.w);
    uint4 u;
    u.x = *reinterpret_cast<uint32_t*>(&h0);
    u.y = *reinterpret_cast<uint32_t*>(&h1);
    u.z = *reinterpret_cast<uint32_t*>(&h2);
    u.w = *reinterpret_cast<uint32_t*>(&h3);
    *reinterpret_cast<uint4*>(g_Xh + i) = u;
}

// ---------------------------------------------------------------------------
// dequant int4 + fold LoRA into Wh (fp16):
//   Wh[o][i] = fp16( (q-z)*s + sum_r At[r][i]*B[r][o] )
// ---------------------------------------------------------------------------
__global__ void dequant_fold_kernel(const int*   __restrict__ packed,
                                    const float* __restrict__ scales,
                                    const float* __restrict__ zeros,
                                    const float* __restrict__ lora_B) {
    const int ib = threadIdx.x;          // 0..255 -> i0 = 8*ib
    const int oq = blockIdx.x;           // 0..1407
    const int i0 = ib * 8;

    float acc[4][8];
#pragma unroll
    for (int j = 0; j < 4; j++)
#pragma unroll
        for (int k = 0; k < 8; k++) acc[j][k] = 0.0f;

#pragma unroll
    for (int r = 0; r < 16; r++) {
        const float4 a0 = *reinterpret_cast<const float4*>(&g_At[r * IN_DIM + i0]);
        const float4 a1 = *reinterpret_cast<const float4*>(&g_At[r * IN_DIM + i0 + 4]);
#pragma unroll
        for (int j = 0; j < 4; j++) {
            const int o = oq + j * (OUT_DIM / 4);
            const float bv = lora_B[r * OUT_DIM + o];
            acc[j][0] += a0.x * bv;  acc[j][1] += a0.y * bv;
            acc[j][2] += a0.z * bv;  acc[j][3] += a0.w * bv;
            acc[j][4] += a1.x * bv;  acc[j][5] += a1.y * bv;
            acc[j][6] += a1.z * bv;  acc[j][7] += a1.w * bv;
        }
    }

#pragma unroll
    for (int j = 0; j < 4; j++) {
        const int o = oq + j * (OUT_DIM / 4);
        const int4 pk = *reinterpret_cast<const int4*>(&packed[(size_t)o * (IN_DIM / 2) + ib * 4]);
        const int g = o * (IN_DIM / GROUP) + (ib >> 4);
        const float s = scales[g];
        const float z = zeros[g];

        int v;
        v = pk.x; acc[j][0] += ((v & 15) - z) * s;  acc[j][1] += (((v >> 4) & 15) - z) * s;
        v = pk.y; acc[j][2] += ((v & 15) - z) * s;  acc[j][3] += (((v >> 4) & 15) - z) * s;
        v = pk.z; acc[j][4] += ((v & 15) - z) * s;  acc[j][5] += (((v >> 4) & 15) - z) * s;
        v = pk.w; acc[j][6] += ((v & 15) - z) * s;  acc[j][7] += (((v >> 4) & 15) - z) * s;

        __half2 h0 = __floats2half2_rn(acc[j][0], acc[j][1]);
        __half2 h1 = __floats2half2_rn(acc[j][2], acc[j][3]);
        __half2 h2 = __floats2half2_rn(acc[j][4], acc[j][5]);
        __half2 h3 = __floats2half2_rn(acc[j][6], acc[j][7]);
        uint4 u;
        u.x = *reinterpret_cast<uint32_t*>(&h0);
        u.y = *reinterpret_cast<uint32_t*>(&h1);
        u.z = *reinterpret_cast<uint32_t*>(&h2);
        u.w = *reinterpret_cast<uint32_t*>(&h3);
        *reinterpret_cast<uint4*>(&g_Wh[(size_t)o * IN_DIM + i0]) = u;
    }
}

// ---------------------------------------------------------------------------
// GEMM: C[8192][5632] = Xh * Wh^T  (fp16 mma.sync m16n8k16, fp32 accum)
// CTA tile 128x128x64h, 256 threads (8 warps = 2x4), warp tile 64x32.
// 3-stage cp.async ring, SW128 xor swizzle, 2 CTAs/SM (regs<=128, smem 96KB).
// ---------------------------------------------------------------------------
__device__ __forceinline__ void ldsm4(uint32_t& r0, uint32_t& r1, uint32_t& r2, uint32_t& r3,
                                      uint32_t addr) {
    asm volatile("ldmatrix.sync.aligned.m8n8.x4.shared.b16 {%0,%1,%2,%3}, [%4];"
                 : "=r"(r0), "=r"(r1), "=r"(r2), "=r"(r3) : "r"(addr));
}

__device__ __forceinline__ void mma_f16(float* d, const uint32_t* a, const uint32_t* b) {
    asm volatile(
        "mma.sync.aligned.m16n8k16.row.col.f32.f16.f16.f32 "
        "{%0,%1,%2,%3}, {%4,%5,%6,%7}, {%8,%9}, {%0,%1,%2,%3};"
        : "+f"(d[0]), "+f"(d[1]), "+f"(d[2]), "+f"(d[3])
        : "r"(a[0]), "r"(a[1]), "r"(a[2]), "r"(a[3]), "r"(b[0]), "r"(b[1]));
}

extern __shared__ char smem_g[];

__global__ __launch_bounds__(256, 2) void gemm_kernel(float* __restrict__ C) {
    const int tid   = threadIdx.x;
    const int lane  = tid & 31;
    const int warp  = tid >> 5;
    const int warpM = warp >> 2;     // 0..1  (64-row slabs)
    const int warpN = warp & 3;      // 0..3  (32-col slabs)
    const int n0 = blockIdx.x * BN;
    const int m0 = blockIdx.y * BM;

    const uint32_t sb = (uint32_t)__cvta_generic_to_shared(smem_g);

    // ---- strength-reduced load plan: 8 x 16B chunks per stage (2048 total)
    // chunk c = tid + i*256; i 0..3 -> A, i 4..7 -> B.
    // row(c) = (tid>>3) + 32*(i mod 4), col = tid&7 (const) -> row&7 const too.
    const int r0c  = tid >> 3;            // base row 0..31
    const int colc = tid & 7;
    const int sw   = (colc ^ (r0c & 7)) << 4;
    const __half* pA = g_Xh + (size_t)(m0 + r0c) * IN_DIM + colc * 8;
    const __half* pB = g_Wh + (size_t)(n0 + r0c) * IN_DIM + colc * 8;
    const uint32_t dA0 = (uint32_t)(r0c * 128 + sw);            // += 4096 per i
    const uint32_t dB0 = (uint32_t)(A_ST + r0c * 128 + sw);

    // ---- ldmatrix per-lane constants
    const int mtx = lane >> 3;       // 8x8 matrix id
    const int x7  = lane & 7;
    const int aRow = warpM * 64 + ((mtx & 1) << 3) + x7;   // A: {0,1}=rows kh0, {2,3}=kh1
    const int kcA  = mtx >> 1;
    const int bRow = warpN * 32 + ((mtx >> 1) << 3) + x7;  // B: {0,1}=n0-7 kh0/1, {2,3}=n8-15
    const int kcB  = mtx & 1;

    float acc[4][4][4];
#pragma unroll
    for (int mi = 0; mi < 4; mi++)
#pragma unroll
        for (int ni = 0; ni < 4; ni++)
#pragma unroll
            for (int e = 0; e < 4; e++) acc[mi][ni][e] = 0.0f;

    // prologue: fill stages 0..1
#pragma unroll
    for (int j = 0; j < STAGES - 1; j++) {
        const uint32_t st = sb + j * ST_BYTES;
#pragma unroll
        for (int i = 0; i < 4; i++) {
            asm volatile("cp.async.cg.shared.global [%0], [%1], 16;"
                         :: "r"(st + dA0 + i * 4096), "l"(pA + (size_t)i * 32 * IN_DIM + j * BKH));
            asm volatile("cp.async.cg.shared.global [%0], [%1], 16;"
                         :: "r"(st + dB0 + i * 4096), "l"(pB + (size_t)i * 32 * IN_DIM + j * BKH));
        }
        asm volatile("cp.async.commit_group;");
    }

    for (int kt = 0; kt < NKT; kt++) {
        asm volatile("cp.async.wait_group 1;");
        __syncthreads();   // stage kt visible; slot (kt+2)%3 free (kt-1 compute done)

        // prefetch stage kt+2 into slot (kt+2)%3
        {
            const int j = kt + STAGES - 1;
            if (j < NKT) {
                const uint32_t st = sb + (j % STAGES) * ST_BYTES;
#pragma unroll
                for (int i = 0; i < 4; i++) {
                    asm volatile("cp.async.cg.shared.global [%0], [%1], 16;"
                                 :: "r"(st + dA0 + i * 4096), "l"(pA + (size_t)i * 32 * IN_DIM + j * BKH));
                    asm volatile("cp.async.cg.shared.global [%0], [%1], 16;"
                                 :: "r"(st + dB0 + i * 4096), "l"(pB + (size_t)i * 32 * IN_DIM + j * BKH));
                }
            }
            asm volatile("cp.async.commit_group;");   // empty at tail keeps counts uniform
        }

        const uint32_t stA = sb + (kt % STAGES) * ST_BYTES;
        const uint32_t stB = stA + (uint32_t)A_ST;

#pragma unroll
        for (int ks = 0; ks < 4; ks++) {   // 4 x k16 covers BKH=64
            uint32_t a[4][4];
#pragma unroll
            for (int mi = 0; mi < 4; mi++) {
                const uint32_t addr = stA + (uint32_t)(aRow + mi * 16) * 128
                                          + ((uint32_t)((ks * 2 + kcA) ^ x7) << 4);
                ldsm4(a[mi][0], a[mi][1], a[mi][2], a[mi][3], addr);
            }
            uint32_t b[4][2];
#pragma unroll
            for (int nb = 0; nb < 2; nb++) {
                uint32_t q0, q1, q2, q3;
                const uint32_t addr = stB + (uint32_t)(bRow + nb * 16) * 128
                                          + ((uint32_t)((ks * 2 + kcB) ^ x7) << 4);
                ldsm4(q0, q1, q2, q3, addr);
                b[nb * 2][0] = q0;      b[nb * 2][1] = q1;
                b[nb * 2 + 1][0] = q2;  b[nb * 2 + 1][1] = q3;
            }
#pragma unroll
            for (int mi = 0; mi < 4; mi++)
#pragma unroll
                for (int ni = 0; ni < 4; ni++)
                    mma_f16(acc[mi][ni], a[mi], b[ni]);
        }
    }

    // epilogue: direct float2 stores
    const int g  = lane >> 2;
    const int t4 = lane & 3;
#pragma unroll
    for (int mi = 0; mi < 4; mi++) {
        const int row = m0 + warpM * 64 + mi * 16 + g;
#pragma unroll
        for (int ni = 0; ni < 4; ni++) {
            const int col = n0 + warpN * 32 + ni * 8 + t4 * 2;
            *reinterpret_cast<float2*>(&C[(size_t)row * OUT_DIM + col]) =
                make_float2(acc[mi][ni][0], acc[mi][ni][1]);
            *reinterpret_cast<float2*>(&C[(size_t)(row + 8) * OUT_DIM + col]) =
                make_float2(acc[mi][ni][2], acc[mi][ni][3]);
        }
    }
}

// ---------------------------------------------------------------------------
extern "C" void kernel_launch(void* const* d_in, const int* in_sizes, int n_in,
                              void* d_out, int out_size) {
    const float* x      = (const float*)d_in[0];
    const int*   packed = (const int*)  d_in[1];
    const float* scales = (const float*)d_in[2];
    const float* zeros  = (const float*)d_in[3];
    const float* lora_A = (const float*)d_in[4];
    const float* lora_B = (const float*)d_in[5];
    float* out = (float*)d_out;

    prep_At_kernel<<<(IN_DIM * 16 + 255) / 256, 256>>>(lora_A);
    conv_x_kernel<<<(int)(((size_t)M_TOT * IN_DIM / 8 + 255) / 256), 256>>>(x);
    dequant_fold_kernel<<<OUT_DIM / 4, 256>>>(packed, scales, zeros, lora_B);

    cudaFuncSetAttribute(gemm_kernel, cudaFuncAttributeMaxDynamicSharedMemorySize,
                         SMEM_TOTAL);
    dim3 grid(OUT_DIM / BN, M_TOT / BM);
    gemm_kernel<<<grid, 256, SMEM_TOTAL>>>(out);
}